// round 13
// baseline (speedup 1.0000x reference)
#include <cuda_runtime.h>
#include <cuda_bf16.h>

#define NA 51   // n_atom

// Scratch for deterministic single-kernel loss reduction (no cudaMalloc allowed).
__device__ float        g_partials[8192];
__device__ unsigned int g_count = 0;

struct RowBuf { float plo[4], phi[4], tlo[4], thi[4]; };

__global__ __launch_bounds__(256) void dtd_kernel(
    const float* __restrict__ dist,          // (B, N, NA)
    const float* __restrict__ next_n_dist,   // (B, N, NA)
    const int*   __restrict__ action,        // (B,)
    const int*   __restrict__ next_n_action, // (B,)
    const float* __restrict__ reward,        // (T, B)
    const unsigned int* __restrict__ done,   // (B,) 32-bit bool encoding
    const float* __restrict__ weight,        // (B,)
    const float* __restrict__ gamma_p,
    const float* __restrict__ vmin_p,
    const float* __restrict__ vmax_p,
    float* __restrict__ out,                 // flattened (loss?, td_err[B])
    int B, int N, int T, int has_loss, int td_off)
{
    __shared__ float    s_log[8][4][64];     // per-warp scratch, reused per group
    __shared__ unsigned s_off[8][32];        // [0:16) dist row off, [16:32) next row off
    __shared__ float    s_w[8];
    __shared__ int      s_last;

    const int warp = threadIdx.x >> 5;
    const int lane = threadIdx.x & 31;
    const int b0   = blockIdx.x * 128 + warp * 16;  // 16 batch elements per warp
    const unsigned FULL = 0xffffffffu;

    const float gamma  = __ldg(gamma_p);
    const float v_min  = __ldg(vmin_p);
    const float v_max  = __ldg(vmax_p);
    const float inv_dz = (float)(NA - 1) / (v_max - v_min);
    const float fMax   = (float)(NA - 1);

    float* __restrict__ td_out = out + td_off;

    // ---- idx phase: wide coalesced LDGs cover all 16 elements' metadata ----
    const int el  = lane & 15;
    const int bce = min(b0 + el, B - 1);
    int idx = (lane < 16) ? __ldg(&action[bce]) : __ldg(&next_n_action[bce]);
    unsigned dmask;
    {
        unsigned dv = (lane < 16) ? __ldg(&done[bce]) : 0u;
        dmask = __ballot_sync(FULL, dv != 0u) & 0xffffu;   // uniform 16-bit done mask
    }
    s_off[warp][lane] = (unsigned)(bce * N + idx) * NA;

    float wlane = 0.0f;
    float rv    = 0.0f;
    if (lane < 16) {
        wlane = __ldg(&weight[bce]);
        float gf = 1.0f;
        for (int t = 0; t < T; t++) {
            rv = fmaf(gf, __ldg(&reward[t * B + bce]), rv);
            gf *= gamma;
        }
    }
    float gT = 1.0f;
    for (int t = 0; t < T; t++) gT *= gamma;
    __syncwarp();

    const float jf0 = (float)lane;
    const float jf1 = (float)(lane + 32);
    float tv = 0.0f;

    // ---- pipeline helpers ----
    auto load_group = [&](int g, RowBuf& rb) {
        #pragma unroll
        for (int i = 0; i < 4; i++) {
            const unsigned op = s_off[warp][g * 4 + i];
            rb.plo[i] = __ldg(&dist[op + lane]);
            rb.phi[i] = (lane < NA - 32) ? __ldg(&dist[op + lane + 32]) : 1.0f;
        }
        #pragma unroll
        for (int i = 0; i < 4; i++) {
            rb.tlo[i] = 0.0f; rb.thi[i] = 0.0f;
            if (!((dmask >> (g * 4 + i)) & 1u)) {        // warp-uniform
                const unsigned ot = s_off[warp][16 + g * 4 + i];
                rb.tlo[i] = __ldg(&next_n_dist[ot + lane]);
                if (lane < NA - 32) rb.thi[i] = __ldg(&next_n_dist[ot + lane + 32]);
            }
        }
    };

    auto compute_group = [&](int g, RowBuf& rb) {
        #pragma unroll
        for (int i = 0; i < 4; i++) {
            s_log[warp][i][lane]      = __logf(rb.plo[i]);
            s_log[warp][i][lane + 32] = __logf(rb.phi[i]);
        }
        __syncwarp();
        float acc[4], dval[4];
        #pragma unroll
        for (int i = 0; i < 4; i++) {
            const float* sl = s_log[warp][i];
            const float ri  = __shfl_sync(FULL, rv, g * 4 + i);
            const bool  dni = (dmask >> (g * 4 + i)) & 1u;
            acc[i] = 0.0f; dval[i] = 0.0f;
            if (dni) {
                // target_z identical across atoms; sum(td)=1 -> one interpolation
                float bb = fminf(fmaxf((ri - v_min) * inv_dz, 0.0f), fMax);
                int   l  = max(__float2int_ru(bb) - 1, 0);
                float fl = (float)l;
                float lo = sl[l], hi = sl[l + 1];
                dval[i] = -fmaf(bb - fl, hi - lo, lo);
            } else {
                // linearized: bb_j = clamp(c + gT*j, 0, NA-1)
                const float c = (fmaf(gT, v_min, ri) - v_min) * inv_dz;
                {   // atoms j = lane
                    float bb = fminf(fmaxf(fmaf(gT, jf0, c), 0.0f), fMax);
                    int   l  = max(__float2int_ru(bb) - 1, 0);
                    float fl = (float)l;
                    float lo = sl[l], hi = sl[l + 1];
                    acc[i] = rb.tlo[i] * fmaf(bb - fl, hi - lo, lo);
                }
                {   // atoms j = lane+32 (thi=0 for lanes >= 19)
                    float bb = fminf(fmaxf(fmaf(gT, jf1, c), 0.0f), fMax);
                    int   l  = max(__float2int_ru(bb) - 1, 0);
                    float fl = (float)l;
                    float lo = sl[l], hi = sl[l + 1];
                    acc[i] = fmaf(rb.thi[i], fmaf(bb - fl, hi - lo, lo), acc[i]);
                }
            }
        }
        #pragma unroll
        for (int i = 0; i < 4; i++) {
            acc[i] += __shfl_xor_sync(FULL, acc[i], 1);
            acc[i] += __shfl_xor_sync(FULL, acc[i], 2);
        }
        const int e = lane & 3;
        float v = acc[0];
        if (e == 1) v = acc[1];
        if (e == 2) v = acc[2];
        if (e == 3) v = acc[3];
        v += __shfl_xor_sync(FULL, v, 4);
        v += __shfl_xor_sync(FULL, v, 8);
        v += __shfl_xor_sync(FULL, v, 16);
        float res = -v;
        float dsel = dval[0];
        if (e == 1) dsel = dval[1];
        if (e == 2) dsel = dval[2];
        if (e == 3) dsel = dval[3];
        if ((dmask >> (g * 4 + e)) & 1u) res = dsel;
        if ((lane >> 2) == g) tv = res;   // element g*4+e lands in lane g*4+e
        __syncwarp();                     // protect s_log reuse by next group
    };

    // ---- depth-3 software pipeline over 4 groups: 2 loads in flight ----
    RowBuf A, Bb, C;
    load_group(0, A);
    load_group(1, Bb);
    load_group(2, C);
    compute_group(0, A);
    load_group(3, A);
    compute_group(1, Bb);
    compute_group(2, C);
    compute_group(3, A);

    // ---- coalesced td_err store (lanes 0-15) + weighted partial ----
    float ws = 0.0f;
    if (lane < 16 && b0 + lane < B) {
        td_out[b0 + lane] = tv;
        ws = tv * wlane;
    }
    ws += __shfl_xor_sync(FULL, ws, 1);
    ws += __shfl_xor_sync(FULL, ws, 2);
    ws += __shfl_xor_sync(FULL, ws, 4);
    ws += __shfl_xor_sync(FULL, ws, 8);
    if (lane == 0) s_w[warp] = ws;
    __syncthreads();

    // ---- block partial + last-block deterministic loss reduction ----
    if (threadIdx.x == 0) {
        float pv = 0.0f;
        #pragma unroll
        for (int w = 0; w < 8; w++) pv += s_w[w];
        g_partials[blockIdx.x] = pv;
        __threadfence();
        unsigned int ticket = atomicAdd(&g_count, 1u);
        s_last = (ticket == gridDim.x - 1) ? 1 : 0;
    }
    __syncthreads();

    if (s_last) {
        __threadfence();
        // Unordered vectorized L2 loads (visible after fence+ticket acquire).
        float pv = 0.0f;
        const int nq = (int)gridDim.x >> 2;
        const float4* gp4 = (const float4*)g_partials;
        for (int i = threadIdx.x; i < nq; i += blockDim.x) {
            float4 q = __ldcg(&gp4[i]);
            pv += (q.x + q.y) + (q.z + q.w);
        }
        for (int i = (nq << 2) + threadIdx.x; i < (int)gridDim.x; i += blockDim.x)
            pv += __ldcg(&g_partials[i]);
        #pragma unroll
        for (int o = 16; o; o >>= 1)
            pv += __shfl_xor_sync(FULL, pv, o);
        if (lane == 0) s_w[warp] = pv;
        __syncthreads();
        if (threadIdx.x < 32) {
            pv = (lane < 8) ? s_w[lane] : 0.0f;
            #pragma unroll
            for (int o = 4; o; o >>= 1)
                pv += __shfl_xor_sync(FULL, pv, o);
            if (threadIdx.x == 0) {
                if (has_loss) out[0] = pv * (1.0f / (float)B);
                g_count = 0;                    // reset for next graph replay
            }
        }
    }
}

extern "C" void kernel_launch(void* const* d_in, const int* in_sizes, int n_in,
                              void* d_out, int out_size)
{
    const float*        dist          = (const float*)d_in[0];
    const float*        next_n_dist   = (const float*)d_in[1];
    const int*          action        = (const int*)d_in[2];
    const int*          next_n_action = (const int*)d_in[3];
    const float*        reward        = (const float*)d_in[4];
    const unsigned int* done          = (const unsigned int*)d_in[5];
    const float*        weight        = (const float*)d_in[6];
    const float*        gamma_p       = (const float*)d_in[7];
    const float*        vmin_p        = (const float*)d_in[8];
    const float*        vmax_p        = (const float*)d_in[9];

    const int B = in_sizes[2];                 // action is (B,)
    const int N = in_sizes[0] / (B * NA);      // dist is (B, N, NA)
    const int T = in_sizes[4] / B;             // reward is (T, B)

    float* out = (float*)d_out;
    const int td_off   = out_size - B;         // td_err is the trailing B elements
    const int has_loss = (out_size > B) ? 1 : 0;

    const int blocks = (B + 127) / 128;        // 128 batch elements per 256-thread block
    dtd_kernel<<<blocks, 256>>>(dist, next_n_dist, action, next_n_action,
                                reward, done, weight, gamma_p, vmin_p, vmax_p,
                                out, B, N, T, has_loss, td_off);
}

// round 14
// speedup vs baseline: 1.1058x; 1.1058x over previous
#include <cuda_runtime.h>
#include <cuda_bf16.h>

#define NA 51   // n_atom

// Scratch for deterministic single-kernel loss reduction (no cudaMalloc allowed).
__device__ float        g_partials[8192];
__device__ unsigned int g_count = 0;

struct RowBuf { float plo[4], phi[4], tlo[4], thi[4]; };

__global__ __launch_bounds__(256) void dtd_kernel(
    const float* __restrict__ dist,          // (B, N, NA)
    const float* __restrict__ next_n_dist,   // (B, N, NA)
    const int*   __restrict__ action,        // (B,)
    const int*   __restrict__ next_n_action, // (B,)
    const float* __restrict__ reward,        // (T, B)
    const unsigned int* __restrict__ done,   // (B,) 32-bit bool encoding
    const float* __restrict__ weight,        // (B,)
    const float* __restrict__ gamma_p,
    const float* __restrict__ vmin_p,
    const float* __restrict__ vmax_p,
    float* __restrict__ out,                 // flattened (loss?, td_err[B])
    int B, int N, int T, int has_loss, int td_off)
{
    __shared__ float    s_log[8][4][64];     // per-warp scratch, reused per group
    __shared__ unsigned s_off[8][16];        // [0:8) dist row off, [8:16) next row off
    __shared__ float    s_w[8];
    __shared__ int      s_last;

    const int warp = threadIdx.x >> 5;
    const int lane = threadIdx.x & 31;
    const int b0   = blockIdx.x * 64 + warp * 8;   // 8 batch elements per warp
    const unsigned FULL = 0xffffffffu;

    const float gamma  = __ldg(gamma_p);
    const float v_min  = __ldg(vmin_p);
    const float v_max  = __ldg(vmax_p);
    const float inv_dz = (float)(NA - 1) / (v_max - v_min);
    const float fMax   = (float)(NA - 1);

    float* __restrict__ td_out = out + td_off;

    // ---- idx phase: wide coalesced LDGs cover all 8 elements' metadata ----
    const int el  = lane & 7;
    const int bce = min(b0 + el, B - 1);
    unsigned dmask;
    {
        unsigned dv = (lane < 8) ? __ldg(&done[bce]) : 0u;
        dmask = __ballot_sync(FULL, dv != 0u) & 0xffu;    // uniform 8-bit done mask
    }
    if (lane < 16) {
        int idx = (lane < 8) ? __ldg(&action[bce]) : __ldg(&next_n_action[bce]);
        s_off[warp][lane] = (unsigned)(bce * N + idx) * NA;
    }

    float wlane = 0.0f;
    float rv    = 0.0f;
    if (lane < 8) {
        wlane = __ldg(&weight[bce]);
        float gf = 1.0f;
        for (int t = 0; t < T; t++) {
            rv = fmaf(gf, __ldg(&reward[t * B + bce]), rv);
            gf *= gamma;
        }
    }
    float gT = 1.0f;
    for (int t = 0; t < T; t++) gT *= gamma;
    __syncwarp();

    const float jf0 = (float)lane;
    const float jf1 = (float)(lane + 32);
    float tv = 0.0f;

    // ---- pipeline helpers ----
    auto load_group = [&](int g, RowBuf& rb) {
        #pragma unroll
        for (int i = 0; i < 4; i++) {
            const unsigned op = s_off[warp][g * 4 + i];
            rb.plo[i] = __ldg(&dist[op + lane]);
            rb.phi[i] = (lane < NA - 32) ? __ldg(&dist[op + lane + 32]) : 1.0f;
        }
        #pragma unroll
        for (int i = 0; i < 4; i++) {
            rb.tlo[i] = 0.0f; rb.thi[i] = 0.0f;
            if (!((dmask >> (g * 4 + i)) & 1u)) {        // warp-uniform
                const unsigned ot = s_off[warp][8 + g * 4 + i];
                rb.tlo[i] = __ldg(&next_n_dist[ot + lane]);
                if (lane < NA - 32) rb.thi[i] = __ldg(&next_n_dist[ot + lane + 32]);
            }
        }
    };

    auto compute_group = [&](int g, RowBuf& rb) {
        #pragma unroll
        for (int i = 0; i < 4; i++) {
            s_log[warp][i][lane]      = __logf(rb.plo[i]);
            s_log[warp][i][lane + 32] = __logf(rb.phi[i]);
        }
        __syncwarp();
        float acc[4], dval[4];
        #pragma unroll
        for (int i = 0; i < 4; i++) {
            const float* sl = s_log[warp][i];
            const float ri  = __shfl_sync(FULL, rv, g * 4 + i);
            const bool  dni = (dmask >> (g * 4 + i)) & 1u;
            acc[i] = 0.0f; dval[i] = 0.0f;
            if (dni) {
                // target_z identical across atoms; sum(td)=1 -> one interpolation
                float bb = fminf(fmaxf((ri - v_min) * inv_dz, 0.0f), fMax);
                int   l  = max(__float2int_ru(bb) - 1, 0);
                float fl = (float)l;
                float lo = sl[l], hi = sl[l + 1];
                dval[i] = -fmaf(bb - fl, hi - lo, lo);
            } else {
                // linearized: bb_j = clamp(c + gT*j, 0, NA-1)
                const float c = (fmaf(gT, v_min, ri) - v_min) * inv_dz;
                {   // atoms j = lane
                    float bb = fminf(fmaxf(fmaf(gT, jf0, c), 0.0f), fMax);
                    int   l  = max(__float2int_ru(bb) - 1, 0);
                    float fl = (float)l;
                    float lo = sl[l], hi = sl[l + 1];
                    acc[i] = rb.tlo[i] * fmaf(bb - fl, hi - lo, lo);
                }
                {   // atoms j = lane+32 (thi=0 for lanes >= 19)
                    float bb = fminf(fmaxf(fmaf(gT, jf1, c), 0.0f), fMax);
                    int   l  = max(__float2int_ru(bb) - 1, 0);
                    float fl = (float)l;
                    float lo = sl[l], hi = sl[l + 1];
                    acc[i] = fmaf(rb.thi[i], fmaf(bb - fl, hi - lo, lo), acc[i]);
                }
            }
        }
        #pragma unroll
        for (int i = 0; i < 4; i++) {
            acc[i] += __shfl_xor_sync(FULL, acc[i], 1);
            acc[i] += __shfl_xor_sync(FULL, acc[i], 2);
        }
        const int e = lane & 3;
        float v = acc[0];
        if (e == 1) v = acc[1];
        if (e == 2) v = acc[2];
        if (e == 3) v = acc[3];
        v += __shfl_xor_sync(FULL, v, 4);
        v += __shfl_xor_sync(FULL, v, 8);
        v += __shfl_xor_sync(FULL, v, 16);
        float res = -v;
        float dsel = dval[0];
        if (e == 1) dsel = dval[1];
        if (e == 2) dsel = dval[2];
        if (e == 3) dsel = dval[3];
        if ((dmask >> (g * 4 + e)) & 1u) res = dsel;
        if ((lane >> 2) == g) tv = res;   // element g*4+e lands in lane g*4+e
        __syncwarp();                     // protect s_log reuse by next group
    };

    // ---- depth-2 software pipeline over 2 groups ----
    RowBuf A, Bb;
    load_group(0, A);
    load_group(1, Bb);
    compute_group(0, A);
    compute_group(1, Bb);

    // ---- coalesced td_err store (lanes 0-7) + weighted partial ----
    float ws = 0.0f;
    if (lane < 8 && b0 + lane < B) {
        td_out[b0 + lane] = tv;
        ws = tv * wlane;
    }
    ws += __shfl_xor_sync(FULL, ws, 1);
    ws += __shfl_xor_sync(FULL, ws, 2);
    ws += __shfl_xor_sync(FULL, ws, 4);
    if (lane == 0) s_w[warp] = ws;
    __syncthreads();

    // ---- block partial + last-block deterministic loss reduction ----
    if (threadIdx.x == 0) {
        float pv = 0.0f;
        #pragma unroll
        for (int w = 0; w < 8; w++) pv += s_w[w];
        g_partials[blockIdx.x] = pv;
        __threadfence();
        unsigned int ticket = atomicAdd(&g_count, 1u);
        s_last = (ticket == gridDim.x - 1) ? 1 : 0;
    }
    __syncthreads();

    if (s_last) {
        __threadfence();
        // Unordered vectorized L2 loads (visible after fence+ticket acquire).
        float pv = 0.0f;
        const int nq = (int)gridDim.x >> 2;
        const float4* gp4 = (const float4*)g_partials;
        for (int i = threadIdx.x; i < nq; i += blockDim.x) {
            float4 q = __ldcg(&gp4[i]);
            pv += (q.x + q.y) + (q.z + q.w);
        }
        for (int i = (nq << 2) + threadIdx.x; i < (int)gridDim.x; i += blockDim.x)
            pv += __ldcg(&g_partials[i]);
        #pragma unroll
        for (int o = 16; o; o >>= 1)
            pv += __shfl_xor_sync(FULL, pv, o);
        if (lane == 0) s_w[warp] = pv;
        __syncthreads();
        if (threadIdx.x < 32) {
            pv = (lane < 8) ? s_w[lane] : 0.0f;
            #pragma unroll
            for (int o = 4; o; o >>= 1)
                pv += __shfl_xor_sync(FULL, pv, o);
            if (threadIdx.x == 0) {
                if (has_loss) out[0] = pv * (1.0f / (float)B);
                g_count = 0;                    // reset for next graph replay
            }
        }
    }
}

extern "C" void kernel_launch(void* const* d_in, const int* in_sizes, int n_in,
                              void* d_out, int out_size)
{
    const float*        dist          = (const float*)d_in[0];
    const float*        next_n_dist   = (const float*)d_in[1];
    const int*          action        = (const int*)d_in[2];
    const int*          next_n_action = (const int*)d_in[3];
    const float*        reward        = (const float*)d_in[4];
    const unsigned int* done          = (const unsigned int*)d_in[5];
    const float*        weight        = (const float*)d_in[6];
    const float*        gamma_p       = (const float*)d_in[7];
    const float*        vmin_p        = (const float*)d_in[8];
    const float*        vmax_p        = (const float*)d_in[9];

    const int B = in_sizes[2];                 // action is (B,)
    const int N = in_sizes[0] / (B * NA);      // dist is (B, N, NA)
    const int T = in_sizes[4] / B;             // reward is (T, B)

    float* out = (float*)d_out;
    const int td_off   = out_size - B;         // td_err is the trailing B elements
    const int has_loss = (out_size > B) ? 1 : 0;

    const int blocks = (B + 63) / 64;          // 64 batch elements per 256-thread block
    dtd_kernel<<<blocks, 256>>>(dist, next_n_dist, action, next_n_action,
                                reward, done, weight, gamma_p, vmin_p, vmax_p,
                                out, B, N, T, has_loss, td_off);
}